// round 14
// baseline (speedup 1.0000x reference)
#include <cuda_runtime.h>
#include <math.h>
#include <stdint.h>

// Problem constants
#define TT   256
#define BB   64
#define EE   512
#define HDD  256
#define NGG  1024         // 4*HD
#define KK   7
#define START_TAG 5
#define STOP_TAG  6
#define NEGV (-10000.0f)
#define RR   (TT*BB)      // 16384 rows
#define HTBUF (HDD*BB)    // 16384 floats per h buffer
#define BF_SPL 8388608u   // g_bf split-plane stride (floats) = 64*32*4096

// ---------------- scratch (static device memory; no allocation) ----------------
__device__ float g_xg[2u * NGG * RR];       // [2048][16384] gate-major input gates
__device__ float g_xT[(size_t)512 * RR];    // layer-1 output, transposed (for feats)
__device__ float g_bT[(size_t)512 * RR];    // gathered emb, transposed: [e][r]
__device__ float g_wf[4u * 64 * 32 * 512];  // w_ih frag-order: [(L*2+s)][tk][lane][tm*4]
__device__ float g_bf[2u * BF_SPL];         // x frag-order: [s][tk][lane][tn*2+j]
__device__ float g_hT[4 * HTBUF];           // [dir*2+parity][col*64+b] h exchange
__device__ float g_feats[RR * KK];
__device__ unsigned char g_bp[TT * BB * 8];
__device__ unsigned int g_flags[2][64 * 8]; // per-CTA step flags, one per 32B sector

// ---------------------------------------------------------------------------------
__device__ __forceinline__ void cpasync16(uint32_t s, const void* g) {
    asm volatile("cp.async.cg.shared.global [%0], [%1], 16;\n" :: "r"(s), "l"(g));
}
__device__ __forceinline__ void cpcommit() { asm volatile("cp.async.commit_group;\n"); }
template<int N> __device__ __forceinline__ void cpwait() {
    asm volatile("cp.async.wait_group %0;\n" :: "n"(N));
}
__device__ __forceinline__ void tf32s(float v, float& hi, float& lo) {
    uint32_t hb; asm("cvt.rna.tf32.f32 %0, %1;" : "=r"(hb) : "f"(v));
    hi = __uint_as_float(hb);
    float l = v - hi;
    uint32_t lb; asm("cvt.rna.tf32.f32 %0, %1;" : "=r"(lb) : "f"(l));
    lo = __uint_as_float(lb);
}
__device__ __forceinline__ void mma8(float* c, const uint32_t* a, const uint32_t* b) {
    asm volatile(
        "mma.sync.aligned.m16n8k8.row.col.f32.tf32.tf32.f32 "
        "{%0,%1,%2,%3},{%4,%5,%6,%7},{%8,%9},{%0,%1,%2,%3};"
        : "+f"(c[0]), "+f"(c[1]), "+f"(c[2]), "+f"(c[3])
        : "r"(a[0]), "r"(a[1]), "r"(a[2]), "r"(a[3]), "r"(b[0]), "r"(b[1]));
}
// packed fp32x2 FMA: acc += w * h (per 32-bit half); b64 operands
__device__ __forceinline__ void fma2(unsigned long long& acc,
                                     unsigned long long w, unsigned long long h) {
    asm volatile("fma.rn.f32x2 %0, %1, %2, %0;" : "+l"(acc) : "l"(w), "l"(h));
}

// =================================================================================
__global__ void reset_flags()
{
    int t = threadIdx.x;
    if (t < 128) g_flags[t >> 6][(t & 63) * 8] = 0u;
}

// =================================================================================
// prep_wf: split w_ih into tf32 hi/lo, stored in mma fragment order.
// =================================================================================
__global__ void __launch_bounds__(256) prep_wf(const float* __restrict__ w_ih)
{
    int tk = blockIdx.x, L = blockIdx.y;
    int t = threadIdx.x, lane = t & 31, g8 = t >> 5;
    const float* W = w_ih + (size_t)L * 2048 * 512;
    int r0 = lane >> 2;
    int kc = tk * 8 + (lane & 3);

    float* dh = g_wf + (((size_t)(L*2 + 0) * 64 + tk) * 32 + lane) * 512;
    float* dl = g_wf + (((size_t)(L*2 + 1) * 64 + tk) * 32 + lane) * 512;

    for (int tm = g8 * 16; tm < g8 * 16 + 16; ++tm) {
        int m = tm * 16 + r0;
        float v0 = W[(size_t)m * 512 + kc];
        float v1 = W[(size_t)(m + 8) * 512 + kc];
        float v2 = W[(size_t)m * 512 + kc + 4];
        float v3 = W[(size_t)(m + 8) * 512 + kc + 4];
        float h0,l0,h1,l1,h2,l2,h3,l3;
        tf32s(v0,h0,l0); tf32s(v1,h1,l1); tf32s(v2,h2,l2); tf32s(v3,h3,l3);
        *(float4*)(dh + tm*4) = make_float4(h0,h1,h2,h3);
        *(float4*)(dl + tm*4) = make_float4(l0,l1,l2,l3);
    }
}

// =================================================================================
// gather embeddings transposed: g_bT[e][r] = emb[sent[r]][e]; 1024 blocks x 256
// =================================================================================
__global__ void __launch_bounds__(256) gather_T(const int* __restrict__ sent,
                                                const float* __restrict__ emb)
{
    __shared__ float sm[16 * 513];
    int t  = threadIdx.x;
    int r0 = blockIdx.x * 16;

#pragma unroll
    for (int i = 0; i < 8; i++) {
        int idx = i * 256 + t;
        int r = idx >> 7, c4 = (idx & 127) * 4;
        float4 v = __ldg((const float4*)(emb + (size_t)sent[r0+r] * 512 + c4));
        sm[r*513 + c4+0] = v.x; sm[r*513 + c4+1] = v.y;
        sm[r*513 + c4+2] = v.z; sm[r*513 + c4+3] = v.w;
    }
    __syncthreads();

    int r = t & 15, e0 = t >> 4;
#pragma unroll
    for (int j = 0; j < 32; j++) {
        int e = j * 16 + e0;
        g_bT[(size_t)e * RR + r0 + r] = sm[r*513 + e];
    }
}

// =================================================================================
// reorder_bf: g_bT -> tf32 hi/lo in B-fragment order.
// =================================================================================
__global__ void __launch_bounds__(256) reorder_bf()
{
    __shared__ float sb[8][516];
    int tk = blockIdx.x, tnb = blockIdx.y;
    int t = threadIdx.x;

#pragma unroll
    for (int i = 0; i < 16; i++) {
        int idx = i * 256 + t;
        int el = idx >> 9, rl = idx & 511;
        sb[el][rl] = g_bT[(size_t)(tk*8 + el) * RR + tnb*512 + rl];
    }
    __syncthreads();

    int lane_o = t >> 3, sub = t & 7;
    float hv[16], lv[16];
#pragma unroll
    for (int tt = 0; tt < 8; tt++) {
        int tn_l = sub * 8 + tt;
#pragma unroll
        for (int j = 0; j < 2; j++) {
            int el = (lane_o & 3) + j * 4;
            int rl = tn_l * 8 + (lane_o >> 2);
            float hi, lo;
            tf32s(sb[el][rl], hi, lo);
            hv[tt*2 + j] = hi;
            lv[tt*2 + j] = lo;
        }
    }
    size_t base = ((size_t)tk * 32 + lane_o) * 4096 + ((size_t)tnb * 64 + sub * 8) * 2;
#pragma unroll
    for (int q = 0; q < 4; q++) {
        *(float4*)(g_bf + base + q*4)          = *(float4*)&hv[q*4];
        *(float4*)(g_bf + BF_SPL + base + q*4) = *(float4*)&lv[q*4];
    }
}

// =================================================================================
// transpose h0 slice for this layer into the parity-1 h buffers (read at s==0)
// =================================================================================
__global__ void prep_layer(int layer, const float* __restrict__ h0)
{
    int d   = blockIdx.y;
    int col = blockIdx.x * 4 + (threadIdx.x >> 6);
    int b   = threadIdx.x & 63;
    g_hT[(d*2 + 1) * HTBUF + col * 64 + b] =
        h0[(2*layer + d) * (BB*HDD) + b * HDD + col];
}

// =================================================================================
// Tensor-core GEMM (3xTF32) — k-chunk 16, 72 KB smem => 2 CTAs/SM (R12 winner).
// =================================================================================
#define GC_BUF 9216                  // floats per buffer (A 4608 + B 4608)

__global__ void __launch_bounds__(256, 2) gemm_tc(
    int L,
    const float* __restrict__ bihL,
    const float* __restrict__ bhhL)
{
    extern __shared__ float smem[];   // 2 buf x GC_BUF floats = 72 KB

    const int t    = threadIdx.x;
    const int lane = t & 31;
    const int w    = t >> 5;
    const int wm   = w >> 1;          // 0..3
    const int wn   = w & 1;           // 0..1
    const int bx   = blockIdx.x;      // n-block 0..127
    const int by   = blockIdx.y;      // m-block 0..15

    float acc[2][8][4];
#pragma unroll
    for (int i = 0; i < 2; i++)
#pragma unroll
        for (int j = 0; j < 8; j++)
#pragma unroll
            for (int q = 0; q < 4; q++) acc[i][j][q] = 0.f;

    auto stage = [&](int c, int buf) {
        float* As = smem + buf * GC_BUF;
        float* Bs = As + 4608;
        int tk0 = c * 2;
#pragma unroll
        for (int i = 0; i < 4; i++) {
            int u = i * 256 + t;                  // 0..1023
            int s   = u >> 9;
            int tkl = (u >> 8) & 1;
            int ln  = (u >> 3) & 31;
            int q   = u & 7;
            int sl  = ((s*2 + tkl) * 32 + ln) * 36 + q * 4;
            const float* ga = g_wf + (((size_t)(L*2 + s) * 64 + tk0 + tkl) * 32 + ln) * 512
                              + by * 32 + q * 4;
            cpasync16((uint32_t)__cvta_generic_to_shared(As + sl), ga);
            const float* gb = g_bf + (size_t)s * BF_SPL
                              + (((size_t)(tk0 + tkl)) * 32 + ln) * 4096 + bx * 32 + q * 4;
            cpasync16((uint32_t)__cvta_generic_to_shared(Bs + sl), gb);
        }
    };

    stage(0, 0); cpcommit();
    stage(1, 1); cpcommit();

    for (int c = 0; c < 32; c++) {
        if (c == 31) cpwait<0>(); else cpwait<1>();
        __syncthreads();
        const float* As = smem + (c & 1) * GC_BUF;
        const float* Bs = As + 4608;

#pragma unroll
        for (int tkl = 0; tkl < 2; tkl++) {
            int s0 = ((0 + tkl) * 32 + lane) * 36;   // hi slice
            int s1 = ((2 + tkl) * 32 + lane) * 36;   // lo slice

            uint32_t ah[2][4], al[2][4];
#pragma unroll
            for (int tmi = 0; tmi < 2; tmi++) {
                float4 vh = *(const float4*)&As[s0 + (wm*2 + tmi) * 4];
                float4 vl = *(const float4*)&As[s1 + (wm*2 + tmi) * 4];
                ah[tmi][0]=__float_as_uint(vh.x); ah[tmi][1]=__float_as_uint(vh.y);
                ah[tmi][2]=__float_as_uint(vh.z); ah[tmi][3]=__float_as_uint(vh.w);
                al[tmi][0]=__float_as_uint(vl.x); al[tmi][1]=__float_as_uint(vl.y);
                al[tmi][2]=__float_as_uint(vl.z); al[tmi][3]=__float_as_uint(vl.w);
            }
            uint32_t bh[8][2], bl[8][2];
#pragma unroll
            for (int tp = 0; tp < 4; tp++) {
                float4 vh = *(const float4*)&Bs[s0 + (wn*8 + tp*2) * 2];
                float4 vl = *(const float4*)&Bs[s1 + (wn*8 + tp*2) * 2];
                bh[tp*2][0]=__float_as_uint(vh.x);   bh[tp*2][1]=__float_as_uint(vh.y);
                bh[tp*2+1][0]=__float_as_uint(vh.z); bh[tp*2+1][1]=__float_as_uint(vh.w);
                bl[tp*2][0]=__float_as_uint(vl.x);   bl[tp*2][1]=__float_as_uint(vl.y);
                bl[tp*2+1][0]=__float_as_uint(vl.z); bl[tp*2+1][1]=__float_as_uint(vl.w);
            }
#pragma unroll
            for (int tmi = 0; tmi < 2; tmi++)
#pragma unroll
                for (int tni = 0; tni < 8; tni++) {
                    mma8(acc[tmi][tni], ah[tmi], bh[tni]);
                    mma8(acc[tmi][tni], ah[tmi], bl[tni]);
                    mma8(acc[tmi][tni], al[tmi], bh[tni]);
                }
        }
        __syncthreads();
        if (c + 2 < 32) { stage(c + 2, c & 1); cpcommit(); }
    }

    // epilogue: bias + store gate-major
#pragma unroll
    for (int tmi = 0; tmi < 2; tmi++) {
        int m = by * 128 + (wm*2 + tmi) * 16 + (lane >> 2);
        float bias0 = __ldg(&bihL[m])     + __ldg(&bhhL[m]);
        float bias8 = __ldg(&bihL[m + 8]) + __ldg(&bhhL[m + 8]);
#pragma unroll
        for (int tni = 0; tni < 8; tni++) {
            int n = bx * 128 + (wn*8 + tni) * 8 + (lane & 3) * 2;
            *(float2*)&g_xg[(size_t)m * RR + n] =
                make_float2(acc[tmi][tni][0] + bias0, acc[tmi][tni][1] + bias0);
            *(float2*)&g_xg[(size_t)(m + 8) * RR + n] =
                make_float2(acc[tmi][tni][2] + bias8, acc[tmi][tni][3] + bias8);
        }
    }
}

// =================================================================================
// Persistent bidirectional LSTM layer — R7 sync structure + PACKED f32x2 mainloop:
// W staged in smem as duplicated pairs (w,w); per k one mov.b64 packs (h_b, h_b+32);
// 16 fma.rn.f32x2 replace 32 FFMA -> mainloop FMA issue halves (4096 -> ~2048 cyc).
// Arithmetic per half is bit-identical to R12 (rel_err must not move).
// =================================================================================
__global__ void __launch_bounds__(512) lstm_layer(
    int layer,
    const float* __restrict__ w_hh,
    const float* __restrict__ c0)
{
    extern __shared__ float sm[];
    float* w_s2 = sm;                // [k=256][o=16] duplicated pairs: 8192 floats, 32 KB
    float* red  = sm + 8192;         // [o=16][sp=16][b=64]  64 KB

    const int d    = blockIdx.y;
    const int cta  = blockIdx.x;     // 0..63
    const int j0   = cta * 4;
    const int tid  = threadIdx.x;
    const int lane = tid & 31;
    const int sp   = tid >> 5;       // 0..15

    const unsigned base = (unsigned)layer * (unsigned)TT;

    // stage this CTA's 16 W rows as duplicated pairs: w_s2[(k*16+o)*2 + {0,1}] = w
    const float* wl = w_hh + (size_t)(layer*2 + d) * 1024 * 256;
    for (int i = tid; i < 4096; i += 512) {
        int o = i >> 8, k = i & 255;
        int g = o >> 2, jj = o & 3;
        float v = wl[(size_t)(g*256 + j0 + jj)*256 + k];
        w_s2[(k*16 + o)*2 + 0] = v;
        w_s2[(k*16 + o)*2 + 1] = v;
    }

    // gate-thread state
    const int gb  = tid & 63;
    const int jl  = (tid >> 6) & 3;
    const int col = j0 + jl;
    float c = 0.f;
    if (tid < 256) c = c0[(2*layer + d)*(BB*HDD) + gb*HDD + col];

    const float* xg = g_xg + (size_t)d * NGG * RR;
    unsigned* myflag   = &g_flags[d][cta * 8];
    unsigned* pollflag = &g_flags[d][(tid & 63) * 8];
    float* hT_d = g_hT + (d*2) * HTBUF;

    const int e = d*256 + col;
    const size_t fo_base = ((size_t)(e >> 3) * 32 + ((gb & 7) * 4 + (e & 3))) * 4096
                           + ((e >> 2) & 1);

    __syncthreads();   // w_s2 ready

    for (int s = 0; s < TT; ++s) {
        int te = d ? (TT - 1 - s) : s;

        // xg prefetch (gate threads; independent of flag wait)
        float xgi = 0.f, xgf = 0.f, xgg = 0.f, xgo = 0.f;
        if (tid < 256) {
            int row = te * 64 + gb;
            xgi = __ldg(&xg[(size_t)(0*256 + col) * RR + row]);
            xgf = __ldg(&xg[(size_t)(1*256 + col) * RR + row]);
            xgg = __ldg(&xg[(size_t)(2*256 + col) * RR + row]);
            xgo = __ldg(&xg[(size_t)(3*256 + col) * RR + row]);
        }

        // wait for all 64 producer flags from step s-1 (2 polling warps)
        if (s > 0 && tid < 64) {
            unsigned tgt = base + (unsigned)s;
            unsigned v;
            do {
                asm volatile("ld.acquire.gpu.global.u32 %0, [%1];" : "=r"(v) : "l"(pollflag));
            } while (v < tgt);
        }
        __syncthreads();   // flags seen by all; also guards red reuse

        // hoisted h loads: 32 outstanding L2 loads, one exposed latency
        const float* hp = hT_d + ((s+1)&1) * HTBUF;
        const int k0 = sp * 16;
        float hv0[16], hv1[16];
#pragma unroll
        for (int kk = 0; kk < 16; ++kk) {
            hv0[kk] = __ldcg(&hp[(k0+kk)*64 + lane]);
            hv1[kk] = __ldcg(&hp[(k0+kk)*64 + lane + 32]);
        }

        unsigned long long acc[16];
#pragma unroll
        for (int o = 0; o < 16; o++) acc[o] = 0ull;   // (0.f, 0.f)

#pragma unroll
        for (int kk = 0; kk < 16; ++kk) {
            int k = k0 + kk;
            unsigned long long hpair;
            asm("mov.b64 %0, {%1, %2};" : "=l"(hpair) : "f"(hv0[kk]), "f"(hv1[kk]));
            const double2* wp = (const double2*)(w_s2 + k * 32);
#pragma unroll
            for (int j = 0; j < 8; ++j) {
                double2 q = wp[j];
                fma2(acc[2*j],     __double_as_longlong(q.x), hpair);
                fma2(acc[2*j + 1], __double_as_longlong(q.y), hpair);
            }
        }
        // unpack + write partials: red[o][sp][b]
#pragma unroll
        for (int o = 0; o < 16; ++o) {
            float a0, a1;
            asm("mov.b64 {%0, %1}, %2;" : "=f"(a0), "=f"(a1) : "l"(acc[o]));
            red[o*1024 + sp*64 + lane]      = a0;
            red[o*1024 + sp*64 + lane + 32] = a1;
        }
        __syncthreads();

        if (tid < 256) {
            float a[4];
#pragma unroll
            for (int g = 0; g < 4; ++g) {
                int o = g*4 + jl;
                float ssum = 0.f;
#pragma unroll
                for (int q = 0; q < 16; ++q) ssum += red[o*1024 + q*64 + gb];
                a[g] = ssum;
            }
            float gi = 1.f / (1.f + expf(-(xgi + a[0])));
            float gf = 1.f / (1.f + expf(-(xgf + a[1])));
            float gg = tanhf(xgg + a[2]);
            float go = 1.f / (1.f + expf(-(xgo + a[3])));
            c = gf * c + gi * gg;
            float h = go * tanhf(c);

            asm volatile("st.global.cg.f32 [%0], %1;"
                         :: "l"(&hT_d[(s&1)*HTBUF + col*64 + gb]), "f"(h) : "memory");

            int r = te * 64 + gb;
            if (layer == 0) {
                float hi, lo;
                tf32s(h, hi, lo);
                size_t fo = fo_base + (size_t)(r >> 3) * 2;
                g_bf[fo]          = hi;
                g_bf[BF_SPL + fo] = lo;
            } else {
                g_xT[(size_t)(d*256 + col) * RR + r] = h;
            }
        }
        __syncthreads();
        if (tid == 0) {
            unsigned v = base + (unsigned)(s + 1);
            asm volatile("st.release.gpu.global.u32 [%0], %1;" :: "l"(myflag), "r"(v) : "memory");
        }
    }
}

// =================================================================================
// feats from transposed input
// =================================================================================
__global__ void __launch_bounds__(128) feats_T(
    const float* __restrict__ wout,
    const float* __restrict__ bout)
{
    __shared__ float ws[512 * 8];
    int tid = threadIdx.x;
    int r = blockIdx.x * 128 + tid;

    for (int i = tid; i < 512 * 8; i += 128) {
        int e = i >> 3, k = i & 7;
        ws[i] = (k < 7) ? __ldg(&wout[k * 512 + e]) : 0.f;
    }
    __syncthreads();

    float acc[8];
#pragma unroll
    for (int k = 0; k < 8; k++) acc[k] = (k < 7) ? __ldg(&bout[k]) : 0.f;

#pragma unroll 4
    for (int e = 0; e < 512; ++e) {
        float x = __ldg(&g_xT[(size_t)e * RR + r]);
        float4 wa = *(const float4*)(ws + e*8);
        float4 wb = *(const float4*)(ws + e*8 + 4);
        acc[0] += x * wa.x; acc[1] += x * wa.y; acc[2] += x * wa.z; acc[3] += x * wa.w;
        acc[4] += x * wb.x; acc[5] += x * wb.y; acc[6] += x * wb.z;
    }
#pragma unroll
    for (int k = 0; k < 7; ++k) g_feats[r * KK + k] = acc[k];
}

// =================================================================================
// Viterbi: 448 threads = 64 batch x 7 next-tags
// =================================================================================
__global__ void viterbi_kernel(const float* __restrict__ trans,
                               void* out, int floatmode)
{
    __shared__ float vbuf[2][64][8];
    __shared__ float tr[7][7];

    int tid = threadIdx.x;
    if (tid < 49) tr[tid / 7][tid % 7] = trans[tid];
    int b  = tid & 63;
    int nx = tid >> 6;
    vbuf[0][b][nx] = (nx == START_TAG) ? 0.f : NEGV;
    __syncthreads();

    int p = 0;
    for (int t = 0; t < TT; ++t) {
        float best = vbuf[p][b][0] + tr[nx][0];
        int   bp   = 0;
#pragma unroll
        for (int pv = 1; pv < 7; ++pv) {
            float cnd = vbuf[p][b][pv] + tr[nx][pv];
            if (cnd > best) { best = cnd; bp = pv; }
        }
        vbuf[p ^ 1][b][nx] = best + g_feats[(t*BB + b) * KK + nx];
        g_bp[(t*BB + b) * 8 + nx] = (unsigned char)bp;
        __syncthreads();
        p ^= 1;
    }

    if (tid < 64) {
        float bestt = vbuf[p][tid][0] + tr[STOP_TAG][0];
        int   lastt = 0;
#pragma unroll
        for (int k2 = 1; k2 < 7; ++k2) {
            float cnd = vbuf[p][tid][k2] + tr[STOP_TAG][k2];
            if (cnd > bestt) { bestt = cnd; lastt = k2; }
        }
        int tag = lastt;
        if (floatmode) {
            float* fo = (float*)out;
            fo[RR + tid] = bestt;
            for (int t = TT - 1; t >= 0; --t) {
                fo[tid * TT + t] = (float)tag;
                tag = g_bp[(t*BB + tid) * 8 + tag];
            }
        } else {
            int* io = (int*)out;
            for (int t = TT - 1; t >= 0; --t) {
                io[tid * TT + t] = tag;
                tag = g_bp[(t*BB + tid) * 8 + tag];
            }
        }
    }
}

// =================================================================================
extern "C" void kernel_launch(void* const* d_in, const int* in_sizes, int n_in,
                              void* d_out, int out_size)
{
    const int*   sent  = (const int*)  d_in[0];
    const float* emb   = (const float*)d_in[1];
    const float* w_ih  = (const float*)d_in[2];
    const float* w_hh  = (const float*)d_in[3];
    const float* b_ih  = (const float*)d_in[4];
    const float* b_hh  = (const float*)d_in[5];
    const float* w_out = (const float*)d_in[6];
    const float* b_out = (const float*)d_in[7];
    const float* trans = (const float*)d_in[8];
    const float* h0    = (const float*)d_in[9];
    const float* c0    = (const float*)d_in[10];

    size_t lsmem = (size_t)(8192 + 16*16*64) * sizeof(float);     // 96 KB
    cudaFuncSetAttribute(lstm_layer, cudaFuncAttributeMaxDynamicSharedMemorySize, (int)lsmem);
    size_t gsmem = (size_t)2 * GC_BUF * sizeof(float);            // 72 KB -> 2 CTAs/SM
    cudaFuncSetAttribute(gemm_tc, cudaFuncAttributeMaxDynamicSharedMemorySize, (int)gsmem);

    dim3 ggrid(128, 16);            // x = n-blocks, y = m-blocks
    dim3 pgrid(64, 2);

    reset_flags<<<1, 128>>>();
    prep_wf<<<dim3(64, 2), 256>>>(w_ih);
    gather_T<<<1024, 256>>>(sent, emb);
    reorder_bf<<<dim3(64, 32), 256>>>();

    prep_layer<<<pgrid, 256>>>(0, h0);
    gemm_tc<<<ggrid, 256, gsmem>>>(0, b_ih + 0*2048, b_hh + 0*2048);
    lstm_layer<<<pgrid, 512, lsmem>>>(0, w_hh, c0);     // overwrites g_bf with h frags

    prep_layer<<<pgrid, 256>>>(1, h0);
    gemm_tc<<<ggrid, 256, gsmem>>>(1, b_ih + 1*2048, b_hh + 1*2048);
    lstm_layer<<<pgrid, 512, lsmem>>>(1, w_hh, c0);

    feats_T<<<128, 128>>>(w_out, b_out);

    int floatmode = (out_size == RR + BB) ? 1 : 0;
    viterbi_kernel<<<1, 448>>>(trans, d_out, floatmode);
}

// round 15
// speedup vs baseline: 1.2342x; 1.2342x over previous
#include <cuda_runtime.h>
#include <math.h>
#include <stdint.h>

// Problem constants
#define TT   256
#define BB   64
#define EE   512
#define HDD  256
#define NGG  1024         // 4*HD
#define KK   7
#define START_TAG 5
#define STOP_TAG  6
#define NEGV (-10000.0f)
#define RR   (TT*BB)      // 16384 rows
#define HTBUF (HDD*BB)    // 16384 floats per h buffer
#define BF_SPL 8388608u   // g_bf split-plane stride (floats) = 64*32*4096

// ---------------- scratch (static device memory; no allocation) ----------------
__device__ float g_xg[2u * NGG * RR];       // [2048][16384] gate-major input gates
__device__ float g_xT[(size_t)512 * RR];    // layer-1 output, transposed (for feats)
__device__ float g_bT[(size_t)512 * RR];    // gathered emb, transposed: [e][r]
__device__ float g_wf[4u * 64 * 32 * 512];  // w_ih frag-order: [(L*2+s)][tk][lane][tm*4]
__device__ float g_bf[2u * BF_SPL];         // x frag-order: [s][tk][lane][tn*2+j]
__device__ float g_hT[4 * HTBUF];           // [dir*2+parity][col*64+b] h exchange
__device__ float g_feats[RR * KK];
__device__ unsigned int g_flags[2][64 * 8]; // per-CTA step flags, one per 32B sector

// ---------------------------------------------------------------------------------
__device__ __forceinline__ void cpasync16(uint32_t s, const void* g) {
    asm volatile("cp.async.cg.shared.global [%0], [%1], 16;\n" :: "r"(s), "l"(g));
}
__device__ __forceinline__ void cpcommit() { asm volatile("cp.async.commit_group;\n"); }
template<int N> __device__ __forceinline__ void cpwait() {
    asm volatile("cp.async.wait_group %0;\n" :: "n"(N));
}
__device__ __forceinline__ void tf32s(float v, float& hi, float& lo) {
    uint32_t hb; asm("cvt.rna.tf32.f32 %0, %1;" : "=r"(hb) : "f"(v));
    hi = __uint_as_float(hb);
    float l = v - hi;
    uint32_t lb; asm("cvt.rna.tf32.f32 %0, %1;" : "=r"(lb) : "f"(l));
    lo = __uint_as_float(lb);
}
__device__ __forceinline__ void mma8(float* c, const uint32_t* a, const uint32_t* b) {
    asm volatile(
        "mma.sync.aligned.m16n8k8.row.col.f32.tf32.tf32.f32 "
        "{%0,%1,%2,%3},{%4,%5,%6,%7},{%8,%9},{%0,%1,%2,%3};"
        : "+f"(c[0]), "+f"(c[1]), "+f"(c[2]), "+f"(c[3])
        : "r"(a[0]), "r"(a[1]), "r"(a[2]), "r"(a[3]), "r"(b[0]), "r"(b[1]));
}

// =================================================================================
__global__ void reset_flags()
{
    int t = threadIdx.x;
    if (t < 128) g_flags[t >> 6][(t & 63) * 8] = 0u;
}

// =================================================================================
// prep_wf: split w_ih into tf32 hi/lo, stored in mma fragment order.
// =================================================================================
__global__ void __launch_bounds__(256) prep_wf(const float* __restrict__ w_ih)
{
    int tk = blockIdx.x, L = blockIdx.y;
    int t = threadIdx.x, lane = t & 31, g8 = t >> 5;
    const float* W = w_ih + (size_t)L * 2048 * 512;
    int r0 = lane >> 2;
    int kc = tk * 8 + (lane & 3);

    float* dh = g_wf + (((size_t)(L*2 + 0) * 64 + tk) * 32 + lane) * 512;
    float* dl = g_wf + (((size_t)(L*2 + 1) * 64 + tk) * 32 + lane) * 512;

    for (int tm = g8 * 16; tm < g8 * 16 + 16; ++tm) {
        int m = tm * 16 + r0;
        float v0 = W[(size_t)m * 512 + kc];
        float v1 = W[(size_t)(m + 8) * 512 + kc];
        float v2 = W[(size_t)m * 512 + kc + 4];
        float v3 = W[(size_t)(m + 8) * 512 + kc + 4];
        float h0,l0,h1,l1,h2,l2,h3,l3;
        tf32s(v0,h0,l0); tf32s(v1,h1,l1); tf32s(v2,h2,l2); tf32s(v3,h3,l3);
        *(float4*)(dh + tm*4) = make_float4(h0,h1,h2,h3);
        *(float4*)(dl + tm*4) = make_float4(l0,l1,l2,l3);
    }
}

// =================================================================================
// gather embeddings transposed: g_bT[e][r] = emb[sent[r]][e]; 1024 blocks x 256
// =================================================================================
__global__ void __launch_bounds__(256) gather_T(const int* __restrict__ sent,
                                                const float* __restrict__ emb)
{
    __shared__ float sm[16 * 513];
    int t  = threadIdx.x;
    int r0 = blockIdx.x * 16;

#pragma unroll
    for (int i = 0; i < 8; i++) {
        int idx = i * 256 + t;
        int r = idx >> 7, c4 = (idx & 127) * 4;
        float4 v = __ldg((const float4*)(emb + (size_t)sent[r0+r] * 512 + c4));
        sm[r*513 + c4+0] = v.x; sm[r*513 + c4+1] = v.y;
        sm[r*513 + c4+2] = v.z; sm[r*513 + c4+3] = v.w;
    }
    __syncthreads();

    int r = t & 15, e0 = t >> 4;
#pragma unroll
    for (int j = 0; j < 32; j++) {
        int e = j * 16 + e0;
        g_bT[(size_t)e * RR + r0 + r] = sm[r*513 + e];
    }
}

// =================================================================================
// reorder_bf: g_bT -> tf32 hi/lo in B-fragment order.
// =================================================================================
__global__ void __launch_bounds__(256) reorder_bf()
{
    __shared__ float sb[8][516];
    int tk = blockIdx.x, tnb = blockIdx.y;
    int t = threadIdx.x;

#pragma unroll
    for (int i = 0; i < 16; i++) {
        int idx = i * 256 + t;
        int el = idx >> 9, rl = idx & 511;
        sb[el][rl] = g_bT[(size_t)(tk*8 + el) * RR + tnb*512 + rl];
    }
    __syncthreads();

    int lane_o = t >> 3, sub = t & 7;
    float hv[16], lv[16];
#pragma unroll
    for (int tt = 0; tt < 8; tt++) {
        int tn_l = sub * 8 + tt;
#pragma unroll
        for (int j = 0; j < 2; j++) {
            int el = (lane_o & 3) + j * 4;
            int rl = tn_l * 8 + (lane_o >> 2);
            float hi, lo;
            tf32s(sb[el][rl], hi, lo);
            hv[tt*2 + j] = hi;
            lv[tt*2 + j] = lo;
        }
    }
    size_t base = ((size_t)tk * 32 + lane_o) * 4096 + ((size_t)tnb * 64 + sub * 8) * 2;
#pragma unroll
    for (int q = 0; q < 4; q++) {
        *(float4*)(g_bf + base + q*4)          = *(float4*)&hv[q*4];
        *(float4*)(g_bf + BF_SPL + base + q*4) = *(float4*)&lv[q*4];
    }
}

// =================================================================================
// transpose h0 slice for this layer into the parity-1 h buffers (read at s==0)
// =================================================================================
__global__ void prep_layer(int layer, const float* __restrict__ h0)
{
    int d   = blockIdx.y;
    int col = blockIdx.x * 4 + (threadIdx.x >> 6);
    int b   = threadIdx.x & 63;
    g_hT[(d*2 + 1) * HTBUF + col * 64 + b] =
        h0[(2*layer + d) * (BB*HDD) + b * HDD + col];
}

// =================================================================================
// Tensor-core GEMM (3xTF32) — k-chunk 16, 72 KB smem => 2 CTAs/SM (R12 winner).
// =================================================================================
#define GC_BUF 9216                  // floats per buffer (A 4608 + B 4608)

__global__ void __launch_bounds__(256, 2) gemm_tc(
    int L,
    const float* __restrict__ bihL,
    const float* __restrict__ bhhL)
{
    extern __shared__ float smem[];   // 2 buf x GC_BUF floats = 72 KB

    const int t    = threadIdx.x;
    const int lane = t & 31;
    const int w    = t >> 5;
    const int wm   = w >> 1;          // 0..3
    const int wn   = w & 1;           // 0..1
    const int bx   = blockIdx.x;      // n-block 0..127
    const int by   = blockIdx.y;      // m-block 0..15

    float acc[2][8][4];
#pragma unroll
    for (int i = 0; i < 2; i++)
#pragma unroll
        for (int j = 0; j < 8; j++)
#pragma unroll
            for (int q = 0; q < 4; q++) acc[i][j][q] = 0.f;

    auto stage = [&](int c, int buf) {
        float* As = smem + buf * GC_BUF;
        float* Bs = As + 4608;
        int tk0 = c * 2;
#pragma unroll
        for (int i = 0; i < 4; i++) {
            int u = i * 256 + t;                  // 0..1023
            int s   = u >> 9;
            int tkl = (u >> 8) & 1;
            int ln  = (u >> 3) & 31;
            int q   = u & 7;
            int sl  = ((s*2 + tkl) * 32 + ln) * 36 + q * 4;
            const float* ga = g_wf + (((size_t)(L*2 + s) * 64 + tk0 + tkl) * 32 + ln) * 512
                              + by * 32 + q * 4;
            cpasync16((uint32_t)__cvta_generic_to_shared(As + sl), ga);
            const float* gb = g_bf + (size_t)s * BF_SPL
                              + (((size_t)(tk0 + tkl)) * 32 + ln) * 4096 + bx * 32 + q * 4;
            cpasync16((uint32_t)__cvta_generic_to_shared(Bs + sl), gb);
        }
    };

    stage(0, 0); cpcommit();
    stage(1, 1); cpcommit();

    for (int c = 0; c < 32; c++) {
        if (c == 31) cpwait<0>(); else cpwait<1>();
        __syncthreads();
        const float* As = smem + (c & 1) * GC_BUF;
        const float* Bs = As + 4608;

#pragma unroll
        for (int tkl = 0; tkl < 2; tkl++) {
            int s0 = ((0 + tkl) * 32 + lane) * 36;   // hi slice
            int s1 = ((2 + tkl) * 32 + lane) * 36;   // lo slice

            uint32_t ah[2][4], al[2][4];
#pragma unroll
            for (int tmi = 0; tmi < 2; tmi++) {
                float4 vh = *(const float4*)&As[s0 + (wm*2 + tmi) * 4];
                float4 vl = *(const float4*)&As[s1 + (wm*2 + tmi) * 4];
                ah[tmi][0]=__float_as_uint(vh.x); ah[tmi][1]=__float_as_uint(vh.y);
                ah[tmi][2]=__float_as_uint(vh.z); ah[tmi][3]=__float_as_uint(vh.w);
                al[tmi][0]=__float_as_uint(vl.x); al[tmi][1]=__float_as_uint(vl.y);
                al[tmi][2]=__float_as_uint(vl.z); al[tmi][3]=__float_as_uint(vl.w);
            }
            uint32_t bh[8][2], bl[8][2];
#pragma unroll
            for (int tp = 0; tp < 4; tp++) {
                float4 vh = *(const float4*)&Bs[s0 + (wn*8 + tp*2) * 2];
                float4 vl = *(const float4*)&Bs[s1 + (wn*8 + tp*2) * 2];
                bh[tp*2][0]=__float_as_uint(vh.x);   bh[tp*2][1]=__float_as_uint(vh.y);
                bh[tp*2+1][0]=__float_as_uint(vh.z); bh[tp*2+1][1]=__float_as_uint(vh.w);
                bl[tp*2][0]=__float_as_uint(vl.x);   bl[tp*2][1]=__float_as_uint(vl.y);
                bl[tp*2+1][0]=__float_as_uint(vl.z); bl[tp*2+1][1]=__float_as_uint(vl.w);
            }
#pragma unroll
            for (int tmi = 0; tmi < 2; tmi++)
#pragma unroll
                for (int tni = 0; tni < 8; tni++) {
                    mma8(acc[tmi][tni], ah[tmi], bh[tni]);
                    mma8(acc[tmi][tni], ah[tmi], bl[tni]);
                    mma8(acc[tmi][tni], al[tmi], bh[tni]);
                }
        }
        __syncthreads();
        if (c + 2 < 32) { stage(c + 2, c & 1); cpcommit(); }
    }

    // epilogue: bias + store gate-major
#pragma unroll
    for (int tmi = 0; tmi < 2; tmi++) {
        int m = by * 128 + (wm*2 + tmi) * 16 + (lane >> 2);
        float bias0 = __ldg(&bihL[m])     + __ldg(&bhhL[m]);
        float bias8 = __ldg(&bihL[m + 8]) + __ldg(&bhhL[m + 8]);
#pragma unroll
        for (int tni = 0; tni < 8; tni++) {
            int n = bx * 128 + (wn*8 + tni) * 8 + (lane & 3) * 2;
            *(float2*)&g_xg[(size_t)m * RR + n] =
                make_float2(acc[tmi][tni][0] + bias0, acc[tmi][tni][1] + bias0);
            *(float2*)&g_xg[(size_t)(m + 8) * RR + n] =
                make_float2(acc[tmi][tni][2] + bias8, acc[tmi][tni][3] + bias8);
        }
    }
}

// =================================================================================
// Persistent bidirectional LSTM layer — R12 configuration (measured optimum).
// =================================================================================
__global__ void __launch_bounds__(512) lstm_layer(
    int layer,
    const float* __restrict__ w_hh,
    const float* __restrict__ c0)
{
    extern __shared__ float sm[];
    float* w_s = sm;                 // [k=256][o=16]  16 KB
    float* red = sm + 256 * 16;      // [o=16][sp=16][b=64]  64 KB

    const int d    = blockIdx.y;
    const int cta  = blockIdx.x;     // 0..63
    const int j0   = cta * 4;
    const int tid  = threadIdx.x;
    const int lane = tid & 31;
    const int sp   = tid >> 5;       // 0..15

    const unsigned base = (unsigned)layer * (unsigned)TT;

    const float* wl = w_hh + (size_t)(layer*2 + d) * 1024 * 256;
    for (int i = tid; i < 4096; i += 512) {
        int o = i >> 8, k = i & 255;
        int g = o >> 2, jj = o & 3;
        w_s[k*16 + o] = wl[(size_t)(g*256 + j0 + jj)*256 + k];
    }

    const int gb  = tid & 63;
    const int jl  = (tid >> 6) & 3;
    const int col = j0 + jl;
    float c = 0.f;
    if (tid < 256) c = c0[(2*layer + d)*(BB*HDD) + gb*HDD + col];

    const float* xg = g_xg + (size_t)d * NGG * RR;
    unsigned* myflag   = &g_flags[d][cta * 8];
    unsigned* pollflag = &g_flags[d][(tid & 63) * 8];
    float* hT_d = g_hT + (d*2) * HTBUF;

    const int e = d*256 + col;
    const size_t fo_base = ((size_t)(e >> 3) * 32 + ((gb & 7) * 4 + (e & 3))) * 4096
                           + ((e >> 2) & 1);

    __syncthreads();   // w_s ready

    for (int s = 0; s < TT; ++s) {
        int te = d ? (TT - 1 - s) : s;

        float xgi = 0.f, xgf = 0.f, xgg = 0.f, xgo = 0.f;
        if (tid < 256) {
            int row = te * 64 + gb;
            xgi = __ldg(&xg[(size_t)(0*256 + col) * RR + row]);
            xgf = __ldg(&xg[(size_t)(1*256 + col) * RR + row]);
            xgg = __ldg(&xg[(size_t)(2*256 + col) * RR + row]);
            xgo = __ldg(&xg[(size_t)(3*256 + col) * RR + row]);
        }

        if (s > 0 && tid < 64) {
            unsigned tgt = base + (unsigned)s;
            unsigned v;
            do {
                asm volatile("ld.acquire.gpu.global.u32 %0, [%1];" : "=r"(v) : "l"(pollflag));
            } while (v < tgt);
        }
        __syncthreads();

        const float* hp = hT_d + ((s+1)&1) * HTBUF;
        const int k0 = sp * 16;
        float hv0[16], hv1[16];
#pragma unroll
        for (int kk = 0; kk < 16; ++kk) {
            hv0[kk] = __ldcg(&hp[(k0+kk)*64 + lane]);
            hv1[kk] = __ldcg(&hp[(k0+kk)*64 + lane + 32]);
        }

        float acc0[16], acc1[16];
#pragma unroll
        for (int o = 0; o < 16; o++) { acc0[o] = 0.f; acc1[o] = 0.f; }
#pragma unroll
        for (int kk = 0; kk < 16; ++kk) {
            int k = k0 + kk;
            float h0v = hv0[kk], h1v = hv1[kk];
            const float4* wp = (const float4*)(w_s + k*16);
            float4 wA = wp[0], wB = wp[1], wC = wp[2], wD = wp[3];
            acc0[ 0] += wA.x*h0v; acc1[ 0] += wA.x*h1v;
            acc0[ 1] += wA.y*h0v; acc1[ 1] += wA.y*h1v;
            acc0[ 2] += wA.z*h0v; acc1[ 2] += wA.z*h1v;
            acc0[ 3] += wA.w*h0v; acc1[ 3] += wA.w*h1v;
            acc0[ 4] += wB.x*h0v; acc1[ 4] += wB.x*h1v;
            acc0[ 5] += wB.y*h0v; acc1[ 5] += wB.y*h1v;
            acc0[ 6] += wB.z*h0v; acc1[ 6] += wB.z*h1v;
            acc0[ 7] += wB.w*h0v; acc1[ 7] += wB.w*h1v;
            acc0[ 8] += wC.x*h0v; acc1[ 8] += wC.x*h1v;
            acc0[ 9] += wC.y*h0v; acc1[ 9] += wC.y*h1v;
            acc0[10] += wC.z*h0v; acc1[10] += wC.z*h1v;
            acc0[11] += wC.w*h0v; acc1[11] += wC.w*h1v;
            acc0[12] += wD.x*h0v; acc1[12] += wD.x*h1v;
            acc0[13] += wD.y*h0v; acc1[13] += wD.y*h1v;
            acc0[14] += wD.z*h0v; acc1[14] += wD.z*h1v;
            acc0[15] += wD.w*h0v; acc1[15] += wD.w*h1v;
        }
#pragma unroll
        for (int o = 0; o < 16; ++o) {
            red[o*1024 + sp*64 + lane]      = acc0[o];
            red[o*1024 + sp*64 + lane + 32] = acc1[o];
        }
        __syncthreads();

        if (tid < 256) {
            float a[4];
#pragma unroll
            for (int g = 0; g < 4; ++g) {
                int o = g*4 + jl;
                float ssum = 0.f;
#pragma unroll
                for (int q = 0; q < 16; ++q) ssum += red[o*1024 + q*64 + gb];
                a[g] = ssum;
            }
            float gi = 1.f / (1.f + expf(-(xgi + a[0])));
            float gf = 1.f / (1.f + expf(-(xgf + a[1])));
            float gg = tanhf(xgg + a[2]);
            float go = 1.f / (1.f + expf(-(xgo + a[3])));
            c = gf * c + gi * gg;
            float h = go * tanhf(c);

            asm volatile("st.global.cg.f32 [%0], %1;"
                         :: "l"(&hT_d[(s&1)*HTBUF + col*64 + gb]), "f"(h) : "memory");

            int r = te * 64 + gb;
            if (layer == 0) {
                float hi, lo;
                tf32s(h, hi, lo);
                size_t fo = fo_base + (size_t)(r >> 3) * 2;
                g_bf[fo]          = hi;
                g_bf[BF_SPL + fo] = lo;
            } else {
                g_xT[(size_t)(d*256 + col) * RR + r] = h;
            }
        }
        __syncthreads();
        if (tid == 0) {
            unsigned v = base + (unsigned)(s + 1);
            asm volatile("st.release.gpu.global.u32 [%0], %1;" :: "l"(myflag), "r"(v) : "memory");
        }
    }
}

// =================================================================================
// feats from transposed input
// =================================================================================
__global__ void __launch_bounds__(128) feats_T(
    const float* __restrict__ wout,
    const float* __restrict__ bout)
{
    __shared__ float ws[512 * 8];
    int tid = threadIdx.x;
    int r = blockIdx.x * 128 + tid;

    for (int i = tid; i < 512 * 8; i += 128) {
        int e = i >> 3, k = i & 7;
        ws[i] = (k < 7) ? __ldg(&wout[k * 512 + e]) : 0.f;
    }
    __syncthreads();

    float acc[8];
#pragma unroll
    for (int k = 0; k < 8; k++) acc[k] = (k < 7) ? __ldg(&bout[k]) : 0.f;

#pragma unroll 4
    for (int e = 0; e < 512; ++e) {
        float x = __ldg(&g_xT[(size_t)e * RR + r]);
        float4 wa = *(const float4*)(ws + e*8);
        float4 wb = *(const float4*)(ws + e*8 + 4);
        acc[0] += x * wa.x; acc[1] += x * wa.y; acc[2] += x * wa.z; acc[3] += x * wa.w;
        acc[4] += x * wb.x; acc[5] += x * wb.y; acc[6] += x * wb.z;
    }
#pragma unroll
    for (int k = 0; k < 7; ++k) g_feats[r * KK + k] = acc[k];
}

// =================================================================================
// Viterbi — latency-optimized: feats software-pipelined (prefetch t+1 into regs
// before computing t) and backpointers kept in 128 KB dynamic SMEM so the
// backtrack is LDS pointer-chasing (~30 cyc/step) instead of L2 (~600 cyc).
// Arithmetic and max/argmax order identical to previous rounds.
// =================================================================================
__global__ void viterbi_kernel(const float* __restrict__ trans,
                               void* out, int floatmode)
{
    extern __shared__ unsigned char dynsm[];
    unsigned char* bp_s = dynsm;                 // [256][64][8] = 131072 B
    __shared__ float vbuf[2][64][8];
    __shared__ float tr[7][7];

    int tid = threadIdx.x;
    if (tid < 49) tr[tid / 7][tid % 7] = trans[tid];
    int b  = tid & 63;
    int nx = tid >> 6;
    vbuf[0][b][nx] = (nx == START_TAG) ? 0.f : NEGV;

    // prefetch feats for t=0
    float fcur = __ldg(&g_feats[(0*BB + b) * KK + nx]);
    __syncthreads();

    int p = 0;
    for (int t = 0; t < TT; ++t) {
        // prefetch next step's feats (hides L2 latency behind compute+barrier)
        float fnext = 0.f;
        if (t + 1 < TT) fnext = __ldg(&g_feats[((t+1)*BB + b) * KK + nx]);

        float best = vbuf[p][b][0] + tr[nx][0];
        int   bp   = 0;
#pragma unroll
        for (int pv = 1; pv < 7; ++pv) {
            float cnd = vbuf[p][b][pv] + tr[nx][pv];
            if (cnd > best) { best = cnd; bp = pv; }
        }
        vbuf[p ^ 1][b][nx] = best + fcur;
        bp_s[(t*BB + b) * 8 + nx] = (unsigned char)bp;
        __syncthreads();
        p ^= 1;
        fcur = fnext;
    }

    if (tid < 64) {
        float bestt = vbuf[p][tid][0] + tr[STOP_TAG][0];
        int   lastt = 0;
#pragma unroll
        for (int k2 = 1; k2 < 7; ++k2) {
            float cnd = vbuf[p][tid][k2] + tr[STOP_TAG][k2];
            if (cnd > bestt) { bestt = cnd; lastt = k2; }
        }
        int tag = lastt;
        if (floatmode) {
            float* fo = (float*)out;
            fo[RR + tid] = bestt;
            for (int t = TT - 1; t >= 0; --t) {
                fo[tid * TT + t] = (float)tag;
                tag = bp_s[(t*BB + tid) * 8 + tag];
            }
        } else {
            int* io = (int*)out;
            for (int t = TT - 1; t >= 0; --t) {
                io[tid * TT + t] = tag;
                tag = bp_s[(t*BB + tid) * 8 + tag];
            }
        }
    }
}

// =================================================================================
extern "C" void kernel_launch(void* const* d_in, const int* in_sizes, int n_in,
                              void* d_out, int out_size)
{
    const int*   sent  = (const int*)  d_in[0];
    const float* emb   = (const float*)d_in[1];
    const float* w_ih  = (const float*)d_in[2];
    const float* w_hh  = (const float*)d_in[3];
    const float* b_ih  = (const float*)d_in[4];
    const float* b_hh  = (const float*)d_in[5];
    const float* w_out = (const float*)d_in[6];
    const float* b_out = (const float*)d_in[7];
    const float* trans = (const float*)d_in[8];
    const float* h0    = (const float*)d_in[9];
    const float* c0    = (const float*)d_in[10];

    size_t lsmem = (size_t)(256*16 + 16*16*64) * sizeof(float);   // 80 KB
    cudaFuncSetAttribute(lstm_layer, cudaFuncAttributeMaxDynamicSharedMemorySize, (int)lsmem);
    size_t gsmem = (size_t)2 * GC_BUF * sizeof(float);            // 72 KB -> 2 CTAs/SM
    cudaFuncSetAttribute(gemm_tc, cudaFuncAttributeMaxDynamicSharedMemorySize, (int)gsmem);
    size_t vsmem = (size_t)TT * BB * 8;                           // 128 KB backpointers
    cudaFuncSetAttribute(viterbi_kernel, cudaFuncAttributeMaxDynamicSharedMemorySize, (int)vsmem);

    dim3 ggrid(128, 16);            // x = n-blocks, y = m-blocks
    dim3 pgrid(64, 2);

    reset_flags<<<1, 128>>>();
    prep_wf<<<dim3(64, 2), 256>>>(w_ih);
    gather_T<<<1024, 256>>>(sent, emb);
    reorder_bf<<<dim3(64, 32), 256>>>();

    prep_layer<<<pgrid, 256>>>(0, h0);
    gemm_tc<<<ggrid, 256, gsmem>>>(0, b_ih + 0*2048, b_hh + 0*2048);
    lstm_layer<<<pgrid, 512, lsmem>>>(0, w_hh, c0);     // overwrites g_bf with h frags

    prep_layer<<<pgrid, 256>>>(1, h0);
    gemm_tc<<<ggrid, 256, gsmem>>>(1, b_ih + 1*2048, b_hh + 1*2048);
    lstm_layer<<<pgrid, 512, lsmem>>>(1, w_hh, c0);

    feats_T<<<128, 128>>>(w_out, b_out);

    int floatmode = (out_size == RR + BB) ? 1 : 0;
    viterbi_kernel<<<1, 448, vsmem>>>(trans, d_out, floatmode);
}